// round 9
// baseline (speedup 1.0000x reference)
#include <cuda_runtime.h>
#include <math.h>

#define TILE 32
#define STR  34          // even, 8B-aligned rows; u64-friendly
#define NT   480
#define SMEM_FLOATS (810 * STR)   // X(405 rows) + Y(405 rows) = 27540 floats = 110160 B

typedef unsigned long long u64;

// ---------------- transposed / padded weight scratch ----------------
// A: [j<53][k<15][q<32(pad of 27)]        -> 53*480
// B: [j<27][l<15][s2<32(pad of 27)]       -> 27*480
// C: [j<27][k<15][q<12(pad of 9)]         -> 27*180
// D: [j<9 ][l<15][s2<12(pad of 9)]        -> 9*180
// E: [j<9 ][k<15][q<8 (pad of 5)]         -> 9*120
// G: [j<5 ][l<15][s2<8 (pad of 5)]        -> 5*120
// F: [j<5 ][k<15]                         -> 75
__device__ float g_wt[46635];
#define OA 0
#define OB 25440
#define OC 38400
#define OD 43260
#define OE 44880
#define OG 45960
#define OF 46560
#define WT_TOTAL 46635

__global__ void tw_kernel(const float* __restrict__ w11, const float* __restrict__ w12,
                          const float* __restrict__ w21, const float* __restrict__ w22,
                          const float* __restrict__ w31, const float* __restrict__ w32,
                          const float* __restrict__ w41) {
    int i = blockIdx.x * blockDim.x + threadIdx.x;
    if (i >= WT_TOTAL) return;
    float v;
    if (i < OB) {
        int j = i / 480, r = i % 480, k = r / 32, q = r % 32;
        v = (q < 27) ? w11[(k * 27 + q) * 53 + j] : 0.f;
    } else if (i < OC) {
        int t = i - OB, j = t / 480, r = t % 480, l = r / 32, q = r % 32;
        v = (q < 27) ? w12[(l * 27 + q) * 27 + j] : 0.f;
    } else if (i < OD) {
        int t = i - OC, j = t / 180, r = t % 180, k = r / 12, q = r % 12;
        v = (q < 9) ? w21[(k * 9 + q) * 27 + j] : 0.f;
    } else if (i < OE) {
        int t = i - OD, j = t / 180, r = t % 180, l = r / 12, q = r % 12;
        v = (q < 9) ? w22[(l * 9 + q) * 9 + j] : 0.f;
    } else if (i < OG) {
        int t = i - OE, j = t / 120, r = t % 120, k = r / 8, q = r % 8;
        v = (q < 5) ? w31[(k * 5 + q) * 9 + j] : 0.f;
    } else if (i < OF) {
        int t = i - OG, j = t / 120, r = t % 120, l = r / 8, q = r % 8;
        v = (q < 5) ? w32[(l * 5 + q) * 5 + j] : 0.f;
    } else {
        int t = i - OF, j = t / 15, k = t % 15;
        v = w41[k * 5 + j];
    }
    g_wt[i] = v;
}

// ---------------- packed f32x2 helpers ----------------
__device__ __forceinline__ u64 dup2(float w) {
    u64 r; asm("mov.b64 %0, {%1, %1};" : "=l"(r) : "f"(w)); return r;
}
__device__ __forceinline__ u64 pack2(float a, float b) {
    u64 r; asm("mov.b64 %0, {%1, %2};" : "=l"(r) : "f"(a), "f"(b)); return r;
}
__device__ __forceinline__ void fma2(u64& d, u64 a, u64 b) {
    asm("fma.rn.f32x2 %0, %1, %2, %0;" : "+l"(d) : "l"(a), "l"(b));
}
__device__ __forceinline__ float2 unp(u64 a) {
    float2 f; asm("mov.b64 {%0, %1}, %2;" : "=f"(f.x), "=f"(f.y) : "l"(a)); return f;
}
__device__ __forceinline__ float gelu_f(float v) {
    return 0.5f * v * (1.0f + erff(v * 0.70710678118654752f));
}

// ---------------- phase A: layer-1 mm1 directly from gmem ----------------
// thread = (k<15, qc<4, sq<8): 8 outputs (qc*8..+7 of group k) x 4 samples (sq*4..+3)
// Input features k*53+j of sample s at x[s*784 + k*53 + j]. For k=14 only j<42 is
// in-range (feature 742..783); j>=42 corresponds to the zero padding -> skip.
__device__ __forceinline__ void phaseA(int tid, const float* __restrict__ x,
                                       int s0, int smax,
                                       float* __restrict__ Out) {
    int k = tid >> 5, qc = (tid >> 3) & 3, sq = tid & 7;
    const float* wb = g_wt + OA + k * 32 + qc * 8;
    int sbase = s0 + sq * 4;
    // clamp sample indices for safety on a ragged tail (outputs for s>=B unused)
    int sa0 = min(sbase + 0, smax), sa1 = min(sbase + 1, smax);
    int sa2 = min(sbase + 2, smax), sa3 = min(sbase + 3, smax);
    const float* p0 = x + (size_t)sa0 * 784 + k * 53;
    const float* p1 = x + (size_t)sa1 * 784 + k * 53;
    const float* p2 = x + (size_t)sa2 * 784 + k * 53;
    const float* p3 = x + (size_t)sa3 * 784 + k * 53;
    const int jmax = (k == 14) ? 42 : 53;
    u64 acc[16];
    #pragma unroll
    for (int u = 0; u < 16; u++) acc[u] = 0ull;
    #pragma unroll 4
    for (int j = 0; j < jmax; j++) {
        float4 w0 = __ldg((const float4*)(wb + j * 480));
        float4 w1 = __ldg((const float4*)(wb + j * 480 + 4));
        u64 i01 = pack2(__ldg(p0 + j), __ldg(p1 + j));
        u64 i23 = pack2(__ldg(p2 + j), __ldg(p3 + j));
        fma2(acc[0],  i01, dup2(w0.x)); fma2(acc[1],  i23, dup2(w0.x));
        fma2(acc[2],  i01, dup2(w0.y)); fma2(acc[3],  i23, dup2(w0.y));
        fma2(acc[4],  i01, dup2(w0.z)); fma2(acc[5],  i23, dup2(w0.z));
        fma2(acc[6],  i01, dup2(w0.w)); fma2(acc[7],  i23, dup2(w0.w));
        fma2(acc[8],  i01, dup2(w1.x)); fma2(acc[9],  i23, dup2(w1.x));
        fma2(acc[10], i01, dup2(w1.y)); fma2(acc[11], i23, dup2(w1.y));
        fma2(acc[12], i01, dup2(w1.z)); fma2(acc[13], i23, dup2(w1.z));
        fma2(acc[14], i01, dup2(w1.w)); fma2(acc[15], i23, dup2(w1.w));
    }
    #pragma unroll
    for (int t = 0; t < 8; t++) {
        int q = qc * 8 + t;
        if (q < 27) {
            float* op = Out + (k * 27 + q) * STR + sq * 4;
            *(float2*)(op)     = unp(acc[2 * t]);
            *(float2*)(op + 2) = unp(acc[2 * t + 1]);
        }
    }
}

// ---------------- phase B: layer-1 permute+mm2+gelu (Y -> X) ----------------
__device__ __forceinline__ void phaseB(int tid, const float* __restrict__ bias,
                                       const float* __restrict__ In,
                                       float* __restrict__ Out) {
    int l = tid >> 5, s2c = (tid >> 3) & 3, sq = tid & 7;
    const float* wb = g_wt + OB + l * 32 + s2c * 8;
    const float* inb = In + l * STR + sq * 4;
    u64 acc[16];
    #pragma unroll
    for (int u = 0; u < 16; u++) acc[u] = 0ull;
    #pragma unroll 4
    for (int j = 0; j < 27; j++) {
        float4 w0 = __ldg((const float4*)(wb + j * 480));
        float4 w1 = __ldg((const float4*)(wb + j * 480 + 4));
        const float* ip = inb + j * 15 * STR;
        u64 i01 = *(const u64*)(ip);
        u64 i23 = *(const u64*)(ip + 2);
        fma2(acc[0],  i01, dup2(w0.x)); fma2(acc[1],  i23, dup2(w0.x));
        fma2(acc[2],  i01, dup2(w0.y)); fma2(acc[3],  i23, dup2(w0.y));
        fma2(acc[4],  i01, dup2(w0.z)); fma2(acc[5],  i23, dup2(w0.z));
        fma2(acc[6],  i01, dup2(w0.w)); fma2(acc[7],  i23, dup2(w0.w));
        fma2(acc[8],  i01, dup2(w1.x)); fma2(acc[9],  i23, dup2(w1.x));
        fma2(acc[10], i01, dup2(w1.y)); fma2(acc[11], i23, dup2(w1.y));
        fma2(acc[12], i01, dup2(w1.z)); fma2(acc[13], i23, dup2(w1.z));
        fma2(acc[14], i01, dup2(w1.w)); fma2(acc[15], i23, dup2(w1.w));
    }
    #pragma unroll
    for (int t = 0; t < 8; t++) {
        int s2 = s2c * 8 + t, f = s2 * 15 + l;
        if (s2 < 27 && f < 392) {
            float bb = bias[f];
            float2 a = unp(acc[2 * t]), b = unp(acc[2 * t + 1]);
            float* op = Out + f * STR + sq * 4;
            *(float2*)(op)     = make_float2(gelu_f(a.x + bb), gelu_f(a.y + bb));
            *(float2*)(op + 2) = make_float2(gelu_f(b.x + bb), gelu_f(b.y + bb));
        }
    }
}

// ---------------- medium phases: 240 threads, NOUT outs x 2 samples ----------------
template<int P, int NOUT, int TPAD>
__device__ __forceinline__ void med_mm1(int tid, const float* __restrict__ Wt,
                                        const float* __restrict__ In,
                                        float* __restrict__ Out) {
    if (tid >= 240) return;
    int k = tid >> 4, sp = tid & 15;
    const float* wb = Wt + k * TPAD;
    const float* inb = In + k * P * STR + sp * 2;
    u64 acc[NOUT];
    #pragma unroll
    for (int t = 0; t < NOUT; t++) acc[t] = 0ull;
    #pragma unroll 4
    for (int j = 0; j < P; j++) {
        u64 in2 = *(const u64*)(inb + j * STR);
        #pragma unroll
        for (int t4 = 0; t4 < TPAD; t4 += 4) {
            float4 w = __ldg((const float4*)(wb + j * (15 * TPAD) + t4));
            if (t4 + 0 < NOUT) fma2(acc[t4 + 0], in2, dup2(w.x));
            if (t4 + 1 < NOUT) fma2(acc[t4 + 1], in2, dup2(w.y));
            if (t4 + 2 < NOUT) fma2(acc[t4 + 2], in2, dup2(w.z));
            if (t4 + 3 < NOUT) fma2(acc[t4 + 3], in2, dup2(w.w));
        }
    }
    #pragma unroll
    for (int t = 0; t < NOUT; t++)
        *(float2*)(Out + (k * NOUT + t) * STR + sp * 2) = unp(acc[t]);
}

template<int P, int NOUT, int TPAD>
__device__ __forceinline__ void med_mm2(int tid, const float* __restrict__ Wt,
                                        const float* __restrict__ bias,
                                        const float* __restrict__ In,
                                        float* __restrict__ Out, int nOut) {
    if (tid >= 240) return;
    int l = tid >> 4, sp = tid & 15;
    const float* wb = Wt + l * TPAD;
    const float* inb = In + l * STR + sp * 2;
    u64 acc[NOUT];
    #pragma unroll
    for (int t = 0; t < NOUT; t++) acc[t] = 0ull;
    #pragma unroll 4
    for (int j = 0; j < P; j++) {
        u64 in2 = *(const u64*)(inb + j * 15 * STR);
        #pragma unroll
        for (int t4 = 0; t4 < TPAD; t4 += 4) {
            float4 w = __ldg((const float4*)(wb + j * (15 * TPAD) + t4));
            if (t4 + 0 < NOUT) fma2(acc[t4 + 0], in2, dup2(w.x));
            if (t4 + 1 < NOUT) fma2(acc[t4 + 1], in2, dup2(w.y));
            if (t4 + 2 < NOUT) fma2(acc[t4 + 2], in2, dup2(w.z));
            if (t4 + 3 < NOUT) fma2(acc[t4 + 3], in2, dup2(w.w));
        }
    }
    #pragma unroll
    for (int t = 0; t < NOUT; t++) {
        int f = t * 15 + l;
        if (f < nOut) {
            float bb = bias[f];
            float2 a = unp(acc[t]);
            *(float2*)(Out + f * STR + sp * 2) =
                make_float2(gelu_f(a.x + bb), gelu_f(a.y + bb));
        }
    }
}

__device__ __forceinline__ void phaseF(int tid, const float* __restrict__ In,
                                       float* __restrict__ Out) {
    if (tid >= 240) return;
    int k = tid >> 4, sp = tid & 15;
    const float* inb = In + k * 5 * STR + sp * 2;
    u64 acc = 0ull;
    #pragma unroll
    for (int j = 0; j < 5; j++) {
        u64 in2 = *(const u64*)(inb + j * STR);
        fma2(acc, in2, dup2(__ldg(g_wt + OF + j * 15 + k)));
    }
    *(float2*)(Out + k * STR + sp * 2) = unp(acc);
}

__device__ __forceinline__ void pad_rows(int tid, float* __restrict__ Out, int lo, int hi) {
    int n = (hi - lo) * TILE;
    for (int i = tid; i < n; i += NT)
        Out[(lo + i / TILE) * STR + (i % TILE)] = 0.f;
}

// ---------------- main fused kernel ----------------
__global__ void __launch_bounds__(NT, 2) monarch_kernel(
    const float* __restrict__ x, int B,
    const float* __restrict__ b1, const float* __restrict__ b2,
    const float* __restrict__ b3, const float* __restrict__ w42,
    const float* __restrict__ b4,
    float* __restrict__ out)
{
    extern __shared__ float sm[];
    float* X = sm;                 // 405 rows x STR
    float* Y = sm + 405 * STR;     // 405 rows x STR
    const int tid = threadIdx.x;
    const int s0 = blockIdx.x * TILE;

    // Layer 1 (input read directly from gmem in phaseA)
    phaseA(tid, x, s0, B - 1, Y);
    __syncthreads();
    phaseB(tid, b1, Y, X);
    pad_rows(tid, X, 392, 405);
    __syncthreads();

    // Layer 2
    med_mm1<27, 9, 12>(tid, g_wt + OC, X, Y);
    __syncthreads();
    med_mm2<9, 9, 12>(tid, g_wt + OD, b2, Y, X, 128);
    pad_rows(tid, X, 128, 135);
    __syncthreads();

    // Layer 3
    med_mm1<9, 5, 8>(tid, g_wt + OE, X, Y);
    __syncthreads();
    med_mm2<5, 5, 8>(tid, g_wt + OG, b3, Y, X, 64);
    pad_rows(tid, X, 64, 75);
    __syncthreads();

    // Layer 4 mm1
    phaseF(tid, X, Y);
    __syncthreads();

    // Layer 4 mm2 + log-softmax
    if (tid < TILE && s0 + tid < B) {
        const int s = tid;
        float logit[10];
        float m = -1e30f;
        #pragma unroll
        for (int l = 0; l < 10; l++) {
            float v = Y[l * STR + s] * w42[l] + b4[l];
            logit[l] = v;
            m = fmaxf(m, v);
        }
        float sum = 0.f;
        #pragma unroll
        for (int l = 0; l < 10; l++) sum += expf(logit[l] - m);
        float lse = m + logf(sum);
        float* op = out + (size_t)(s0 + s) * 10;
        #pragma unroll
        for (int l = 0; l < 10; l++) op[l] = logit[l] - lse;
    }
}

extern "C" void kernel_launch(void* const* d_in, const int* in_sizes, int n_in,
                              void* d_out, int out_size) {
    const float* x   = (const float*)d_in[0];
    const float* w11 = (const float*)d_in[1];
    const float* w12 = (const float*)d_in[2];
    const float* b1  = (const float*)d_in[3];
    const float* w21 = (const float*)d_in[4];
    const float* w22 = (const float*)d_in[5];
    const float* b2  = (const float*)d_in[6];
    const float* w31 = (const float*)d_in[7];
    const float* w32 = (const float*)d_in[8];
    const float* b3  = (const float*)d_in[9];
    const float* w41 = (const float*)d_in[10];
    const float* w42 = (const float*)d_in[11];
    const float* b4  = (const float*)d_in[12];
    float* out = (float*)d_out;

    int B = in_sizes[0] / 784;

    tw_kernel<<<(WT_TOTAL + 255) / 256, 256>>>(w11, w12, w21, w22, w31, w32, w41);

    int grid = (B + TILE - 1) / TILE;
    size_t smem = SMEM_FLOATS * sizeof(float);
    cudaFuncSetAttribute(monarch_kernel,
                         cudaFuncAttributeMaxDynamicSharedMemorySize, (int)smem);
    monarch_kernel<<<grid, NT, smem>>>(x, B, b1, b2, b3, w42, b4, out);
}

// round 10
// speedup vs baseline: 1.5140x; 1.5140x over previous
#include <cuda_runtime.h>
#include <math.h>

#define TILE 32
#define HALF 16
#define STR  34          // Y/X row stride (even -> u64-aligned sample pairs)
#define SSTR 795         // staging stride, odd -> conflict-free strided LDS
#define NT   480
#define R0_FLOATS (405 * STR)                 // region0: X (also covers staging 16*795=12720 < 13770)
#define SMEM_FLOATS (R0_FLOATS + 405 * STR)   // 27540 floats = 110160 B -> 2 blocks/SM

typedef unsigned long long u64;

// ---------------- transposed / padded weight scratch ----------------
// A: [j<53][k<15][q<32(pad of 27)]        -> 53*480
// B: [j<27][l<15][s2<32(pad of 27)]       -> 27*480
// C: [j<27][k<15][q<12(pad of 9)]         -> 27*180
// D: [j<9 ][l<15][s2<12(pad of 9)]        -> 9*180
// E: [j<9 ][k<15][q<8 (pad of 5)]         -> 9*120
// G: [j<5 ][l<15][s2<8 (pad of 5)]        -> 5*120
// F: [j<5 ][k<15]                         -> 75
__device__ float g_wt[46635];
#define OA 0
#define OB 25440
#define OC 38400
#define OD 43260
#define OE 44880
#define OG 45960
#define OF 46560
#define WT_TOTAL 46635

__global__ void tw_kernel(const float* __restrict__ w11, const float* __restrict__ w12,
                          const float* __restrict__ w21, const float* __restrict__ w22,
                          const float* __restrict__ w31, const float* __restrict__ w32,
                          const float* __restrict__ w41) {
    int i = blockIdx.x * blockDim.x + threadIdx.x;
    if (i >= WT_TOTAL) return;
    float v;
    if (i < OB) {
        int j = i / 480, r = i % 480, k = r / 32, q = r % 32;
        v = (q < 27) ? w11[(k * 27 + q) * 53 + j] : 0.f;
    } else if (i < OC) {
        int t = i - OB, j = t / 480, r = t % 480, l = r / 32, q = r % 32;
        v = (q < 27) ? w12[(l * 27 + q) * 27 + j] : 0.f;
    } else if (i < OD) {
        int t = i - OC, j = t / 180, r = t % 180, k = r / 12, q = r % 12;
        v = (q < 9) ? w21[(k * 9 + q) * 27 + j] : 0.f;
    } else if (i < OE) {
        int t = i - OD, j = t / 180, r = t % 180, l = r / 12, q = r % 12;
        v = (q < 9) ? w22[(l * 9 + q) * 9 + j] : 0.f;
    } else if (i < OG) {
        int t = i - OE, j = t / 120, r = t % 120, k = r / 8, q = r % 8;
        v = (q < 5) ? w31[(k * 5 + q) * 9 + j] : 0.f;
    } else if (i < OF) {
        int t = i - OG, j = t / 120, r = t % 120, l = r / 8, q = r % 8;
        v = (q < 5) ? w32[(l * 5 + q) * 5 + j] : 0.f;
    } else {
        int t = i - OF, j = t / 15, k = t % 15;
        v = w41[k * 5 + j];
    }
    g_wt[i] = v;
}

// ---------------- packed f32x2 helpers ----------------
__device__ __forceinline__ u64 dup2(float w) {
    u64 r; asm("mov.b64 %0, {%1, %1};" : "=l"(r) : "f"(w)); return r;
}
__device__ __forceinline__ u64 pack2(float a, float b) {
    u64 r; asm("mov.b64 %0, {%1, %2};" : "=l"(r) : "f"(a), "f"(b)); return r;
}
__device__ __forceinline__ void fma2(u64& d, u64 a, u64 b) {
    asm("fma.rn.f32x2 %0, %1, %2, %0;" : "+l"(d) : "l"(a), "l"(b));
}
__device__ __forceinline__ float2 unp(u64 a) {
    float2 f; asm("mov.b64 {%0, %1}, %2;" : "=f"(f.x), "=f"(f.y) : "l"(a)); return f;
}
__device__ __forceinline__ float gelu_f(float v) {
    return 0.5f * v * (1.0f + erff(v * 0.70710678118654752f));
}

// ---------------- phase A: layer-1 mm1 from staged 16-sample half ----------------
// thread = (k<15, qc<4, sq<8): 8 outputs (qc*8..+7 of group k) x 2 samples (2sq,2sq+1)
__device__ __forceinline__ void phaseA(int tid, const float* __restrict__ S,
                                       int h0, float* __restrict__ Out) {
    int k = tid >> 5, qc = (tid >> 3) & 3, sq = tid & 7;
    const float* wb = g_wt + OA + k * 32 + qc * 8;
    const float* inb = S + (sq * 2) * SSTR + k * 53;
    u64 acc[8];
    #pragma unroll
    for (int u = 0; u < 8; u++) acc[u] = 0ull;
    #pragma unroll 4
    for (int j = 0; j < 53; j++) {
        float4 w0 = __ldg((const float4*)(wb + j * 480));
        float4 w1 = __ldg((const float4*)(wb + j * 480 + 4));
        u64 in2 = pack2(inb[j], inb[SSTR + j]);
        fma2(acc[0], in2, dup2(w0.x));
        fma2(acc[1], in2, dup2(w0.y));
        fma2(acc[2], in2, dup2(w0.z));
        fma2(acc[3], in2, dup2(w0.w));
        fma2(acc[4], in2, dup2(w1.x));
        fma2(acc[5], in2, dup2(w1.y));
        fma2(acc[6], in2, dup2(w1.z));
        fma2(acc[7], in2, dup2(w1.w));
    }
    #pragma unroll
    for (int t = 0; t < 8; t++) {
        int q = qc * 8 + t;
        if (q < 27)
            *(float2*)(Out + (k * 27 + q) * STR + h0 + sq * 2) = unp(acc[t]);
    }
}

// ---------------- phase B: layer-1 permute+mm2+gelu over all 32 samples ----------------
__device__ __forceinline__ void phaseB(int tid, const float* __restrict__ bias,
                                       const float* __restrict__ In,
                                       float* __restrict__ Out) {
    int l = tid >> 5, s2c = (tid >> 3) & 3, sq = tid & 7;
    const float* wb = g_wt + OB + l * 32 + s2c * 8;
    const float* inb = In + l * STR + sq * 4;
    u64 acc[16];
    #pragma unroll
    for (int u = 0; u < 16; u++) acc[u] = 0ull;
    #pragma unroll 4
    for (int j = 0; j < 27; j++) {
        float4 w0 = __ldg((const float4*)(wb + j * 480));
        float4 w1 = __ldg((const float4*)(wb + j * 480 + 4));
        const float* ip = inb + j * 15 * STR;
        u64 i01 = *(const u64*)(ip);
        u64 i23 = *(const u64*)(ip + 2);
        fma2(acc[0],  i01, dup2(w0.x)); fma2(acc[1],  i23, dup2(w0.x));
        fma2(acc[2],  i01, dup2(w0.y)); fma2(acc[3],  i23, dup2(w0.y));
        fma2(acc[4],  i01, dup2(w0.z)); fma2(acc[5],  i23, dup2(w0.z));
        fma2(acc[6],  i01, dup2(w0.w)); fma2(acc[7],  i23, dup2(w0.w));
        fma2(acc[8],  i01, dup2(w1.x)); fma2(acc[9],  i23, dup2(w1.x));
        fma2(acc[10], i01, dup2(w1.y)); fma2(acc[11], i23, dup2(w1.y));
        fma2(acc[12], i01, dup2(w1.z)); fma2(acc[13], i23, dup2(w1.z));
        fma2(acc[14], i01, dup2(w1.w)); fma2(acc[15], i23, dup2(w1.w));
    }
    #pragma unroll
    for (int t = 0; t < 8; t++) {
        int s2 = s2c * 8 + t, f = s2 * 15 + l;
        if (s2 < 27 && f < 392) {
            float bb = bias[f];
            float2 a = unp(acc[2 * t]), b = unp(acc[2 * t + 1]);
            float* op = Out + f * STR + sq * 4;
            *(float2*)(op)     = make_float2(gelu_f(a.x + bb), gelu_f(a.y + bb));
            *(float2*)(op + 2) = make_float2(gelu_f(b.x + bb), gelu_f(b.y + bb));
        }
    }
}

// ---------------- medium phases: 240 threads, NOUT outs x 2 samples ----------------
template<int P, int NOUT, int TPAD>
__device__ __forceinline__ void med_mm1(int tid, const float* __restrict__ Wt,
                                        const float* __restrict__ In,
                                        float* __restrict__ Out) {
    if (tid >= 240) return;
    int k = tid >> 4, sp = tid & 15;
    const float* wb = Wt + k * TPAD;
    const float* inb = In + k * P * STR + sp * 2;
    u64 acc[NOUT];
    #pragma unroll
    for (int t = 0; t < NOUT; t++) acc[t] = 0ull;
    #pragma unroll 4
    for (int j = 0; j < P; j++) {
        u64 in2 = *(const u64*)(inb + j * STR);
        #pragma unroll
        for (int t4 = 0; t4 < TPAD; t4 += 4) {
            float4 w = __ldg((const float4*)(wb + j * (15 * TPAD) + t4));
            if (t4 + 0 < NOUT) fma2(acc[t4 + 0], in2, dup2(w.x));
            if (t4 + 1 < NOUT) fma2(acc[t4 + 1], in2, dup2(w.y));
            if (t4 + 2 < NOUT) fma2(acc[t4 + 2], in2, dup2(w.z));
            if (t4 + 3 < NOUT) fma2(acc[t4 + 3], in2, dup2(w.w));
        }
    }
    #pragma unroll
    for (int t = 0; t < NOUT; t++)
        *(float2*)(Out + (k * NOUT + t) * STR + sp * 2) = unp(acc[t]);
}

template<int P, int NOUT, int TPAD>
__device__ __forceinline__ void med_mm2(int tid, const float* __restrict__ Wt,
                                        const float* __restrict__ bias,
                                        const float* __restrict__ In,
                                        float* __restrict__ Out, int nOut) {
    if (tid >= 240) return;
    int l = tid >> 4, sp = tid & 15;
    const float* wb = Wt + l * TPAD;
    const float* inb = In + l * STR + sp * 2;
    u64 acc[NOUT];
    #pragma unroll
    for (int t = 0; t < NOUT; t++) acc[t] = 0ull;
    #pragma unroll 4
    for (int j = 0; j < P; j++) {
        u64 in2 = *(const u64*)(inb + j * 15 * STR);
        #pragma unroll
        for (int t4 = 0; t4 < TPAD; t4 += 4) {
            float4 w = __ldg((const float4*)(wb + j * (15 * TPAD) + t4));
            if (t4 + 0 < NOUT) fma2(acc[t4 + 0], in2, dup2(w.x));
            if (t4 + 1 < NOUT) fma2(acc[t4 + 1], in2, dup2(w.y));
            if (t4 + 2 < NOUT) fma2(acc[t4 + 2], in2, dup2(w.z));
            if (t4 + 3 < NOUT) fma2(acc[t4 + 3], in2, dup2(w.w));
        }
    }
    #pragma unroll
    for (int t = 0; t < NOUT; t++) {
        int f = t * 15 + l;
        if (f < nOut) {
            float bb = bias[f];
            float2 a = unp(acc[t]);
            *(float2*)(Out + f * STR + sp * 2) =
                make_float2(gelu_f(a.x + bb), gelu_f(a.y + bb));
        }
    }
}

__device__ __forceinline__ void phaseF(int tid, const float* __restrict__ In,
                                       float* __restrict__ Out) {
    if (tid >= 240) return;
    int k = tid >> 4, sp = tid & 15;
    const float* inb = In + k * 5 * STR + sp * 2;
    u64 acc = 0ull;
    #pragma unroll
    for (int j = 0; j < 5; j++) {
        u64 in2 = *(const u64*)(inb + j * STR);
        fma2(acc, in2, dup2(__ldg(g_wt + OF + j * 15 + k)));
    }
    *(float2*)(Out + k * STR + sp * 2) = unp(acc);
}

__device__ __forceinline__ void load_half(int tid, const float* __restrict__ x,
                                          int sbase, int B, float* __restrict__ S) {
    const float* xb = x + (size_t)sbase * 784;
    for (int idx = tid; idx < HALF * 196; idx += NT) {
        int s = idx / 196, c4 = idx - s * 196;
        float4 v = make_float4(0.f, 0.f, 0.f, 0.f);
        if (sbase + s < B) v = __ldcg((const float4*)xb + idx);
        float* d = S + s * SSTR + c4 * 4;
        d[0] = v.x; d[1] = v.y; d[2] = v.z; d[3] = v.w;
    }
    for (int i = tid; i < HALF * 11; i += NT)
        S[(i / 11) * SSTR + 784 + (i % 11)] = 0.f;
}

__device__ __forceinline__ void pad_rows(int tid, float* __restrict__ Out, int lo, int hi) {
    int n = (hi - lo) * TILE;
    for (int i = tid; i < n; i += NT)
        Out[(lo + i / TILE) * STR + (i % TILE)] = 0.f;
}

// ---------------- main fused kernel ----------------
__global__ void __launch_bounds__(NT, 2) monarch_kernel(
    const float* __restrict__ x, int B,
    const float* __restrict__ b1, const float* __restrict__ b2,
    const float* __restrict__ b3, const float* __restrict__ w42,
    const float* __restrict__ b4,
    float* __restrict__ out)
{
    extern __shared__ float sm[];
    float* S = sm;                  // staging: 16 x SSTR (fits inside region0)
    float* X = sm;                  // layers 2+ activations (region0, aliases staging)
    float* Y = sm + R0_FLOATS;      // 405 rows x STR
    const int tid = threadIdx.x;
    const int s0 = blockIdx.x * TILE;

    // Layer 1 mm1, in two 16-sample halves through the small staging buffer
    load_half(tid, x, s0, B, S);
    __syncthreads();
    phaseA(tid, S, 0, Y);
    __syncthreads();
    load_half(tid, x, s0 + HALF, B, S);
    __syncthreads();
    phaseA(tid, S, HALF, Y);
    __syncthreads();

    // Layer 1 mm2 (+permute, bias, gelu): Y -> X (X overwrites staging; staging dead)
    phaseB(tid, b1, Y, X);
    pad_rows(tid, X, 392, 405);
    __syncthreads();

    // Layer 2
    med_mm1<27, 9, 12>(tid, g_wt + OC, X, Y);
    __syncthreads();
    med_mm2<9, 9, 12>(tid, g_wt + OD, b2, Y, X, 128);
    pad_rows(tid, X, 128, 135);
    __syncthreads();

    // Layer 3
    med_mm1<9, 5, 8>(tid, g_wt + OE, X, Y);
    __syncthreads();
    med_mm2<5, 5, 8>(tid, g_wt + OG, b3, Y, X, 64);
    pad_rows(tid, X, 64, 75);
    __syncthreads();

    // Layer 4 mm1
    phaseF(tid, X, Y);
    __syncthreads();

    // Layer 4 mm2 + log-softmax
    if (tid < TILE && s0 + tid < B) {
        const int s = tid;
        float logit[10];
        float m = -1e30f;
        #pragma unroll
        for (int l = 0; l < 10; l++) {
            float v = Y[l * STR + s] * w42[l] + b4[l];
            logit[l] = v;
            m = fmaxf(m, v);
        }
        float sum = 0.f;
        #pragma unroll
        for (int l = 0; l < 10; l++) sum += expf(logit[l] - m);
        float lse = m + logf(sum);
        float* op = out + (size_t)(s0 + s) * 10;
        #pragma unroll
        for (int l = 0; l < 10; l++) op[l] = logit[l] - lse;
    }
}

extern "C" void kernel_launch(void* const* d_in, const int* in_sizes, int n_in,
                              void* d_out, int out_size) {
    const float* x   = (const float*)d_in[0];
    const float* w11 = (const float*)d_in[1];
    const float* w12 = (const float*)d_in[2];
    const float* b1  = (const float*)d_in[3];
    const float* w21 = (const float*)d_in[4];
    const float* w22 = (const float*)d_in[5];
    const float* b2  = (const float*)d_in[6];
    const float* w31 = (const float*)d_in[7];
    const float* w32 = (const float*)d_in[8];
    const float* b3  = (const float*)d_in[9];
    const float* w41 = (const float*)d_in[10];
    const float* w42 = (const float*)d_in[11];
    const float* b4  = (const float*)d_in[12];
    float* out = (float*)d_out;

    int B = in_sizes[0] / 784;

    tw_kernel<<<(WT_TOTAL + 255) / 256, 256>>>(w11, w12, w21, w22, w31, w32, w41);

    int grid = (B + TILE - 1) / TILE;
    size_t smem = SMEM_FLOATS * sizeof(float);
    cudaFuncSetAttribute(monarch_kernel,
                         cudaFuncAttributeMaxDynamicSharedMemorySize, (int)smem);
    monarch_kernel<<<grid, NT, smem>>>(x, B, b1, b2, b3, w42, b4, out);
}